// round 15
// baseline (speedup 1.0000x reference)
#include <cuda_runtime.h>
#include <cuda_bf16.h>

// Problem: MultinomialCELoss
//   x: [N=8, Q=441, H=128, W=128] f32, y: [N=8, 2, H=128, W=128] f32
//   out[w] = -sum_{n,h} log( x[n, idx(n,h,w), h, w] )
//
// R15: warm replays are L2-resident; the binder is L1tex WAVEFRONTS, not
// DRAM. R11's column layout makes every y load 32-lines-per-warp (2048
// wavefronts/CTA, 2/3 of total). Re-tile: warp spans 32 consecutive w at a
// fixed (n,h) row -> y loads fully coalesced (1 wavefront), gathers unchanged
// (irreducibly scattered). Grid = 4 w-groups x 32 row-chunks; cross-CTA
// combine via slice-padded REDG + R10's fence-free counter tail (~+0.2us).

#define N_  8
#define Q_  441
#define H_  128
#define W_  128
#define HW_ (H_ * W_)
#define NBINS 21
#define PAD 64                   // 256B stride: spread accs across L2 slices
#define TPB 512
#define GRID 128                 // 4 w-groups x 32 row-chunks
#define ROWS_PER_WARP 2

__device__ float g_acc[W_ * PAD];    // zero-initialized at module load
__device__ unsigned int g_count;     // zero-initialized at module load

__device__ __forceinline__ int ab_bin(float v) {
    // Match JAX f32 semantics: floor((v + 110) / 10), clipped to [0,20].
    // __fdiv_rn keeps IEEE division even under fast-math (bin boundaries).
    float q = floorf(__fdiv_rn(v + 110.0f, 10.0f));
    int qi = (int)q;
    qi = qi < 0 ? 0 : qi;
    qi = qi > (NBINS - 1) ? (NBINS - 1) : qi;
    return qi;
}

__global__ __launch_bounds__(TPB) void mce_tiled_kernel(
    const float* __restrict__ x,
    const float* __restrict__ y,
    float* __restrict__ out)
{
    const int t = threadIdx.x;            // 0..511
    const int lane = t & 31;              // w within group
    const int wrp = t >> 5;               // 0..15
    const int wg = blockIdx.x & 3;        // w-group: w0 = 32*wg
    const int chunk = blockIdx.x >> 2;    // 0..31: rows [32*chunk, 32*chunk+32)
    const int w = wg * 32 + lane;

    // Each warp handles 2 rows; lane = w offset -> ALL loads coalesced
    // except the inherently-scattered x gather.
    float s = 0.0f;
    int idx[ROWS_PER_WARP], n_[ROWS_PER_WARP], hw_[ROWS_PER_WARP];
    #pragma unroll
    for (int k = 0; k < ROWS_PER_WARP; k++) {
        const int row = chunk * 32 + wrp * ROWS_PER_WARP + k;  // 0..1023
        const int n = row >> 7;
        const int h = row & (H_ - 1);
        n_[k] = n;
        hw_[k] = h * W_ + w;
        float ya = y[(size_t)(n * 2 + 0) * HW_ + hw_[k]];   // 1 wavefront
        float yb = y[(size_t)(n * 2 + 1) * HW_ + hw_[k]];   // 1 wavefront
        idx[k] = ab_bin(ya) * NBINS + ab_bin(yb);
    }

    float v[ROWS_PER_WARP];
    #pragma unroll
    for (int k = 0; k < ROWS_PER_WARP; k++) {
        v[k] = x[((size_t)n_[k] * Q_ + idx[k]) * HW_ + hw_[k]];
    }
    #pragma unroll
    for (int k = 0; k < ROWS_PER_WARP; k++) s += __logf(v[k]);

    // Per-CTA reduction over the 16 warps (same w per lane across warps).
    __shared__ float red[16][32];
    red[wrp][lane] = s;
    __syncthreads();

    if (t < 32) {
        float c = 0.0f;
        #pragma unroll
        for (int j = 0; j < 16; j++) c += red[j][t];
        // REDG-with-return into slice-padded accumulator; consuming the
        // return makes the later counter bump provably ordered after it.
        float old = atomicAdd(&g_acc[(wg * 32 + t) * PAD], c);
        red[0][t] = old;   // consume return value (kept by compiler)
    }
    __syncthreads();

    __shared__ unsigned int s_last;
    if (t == 0) {
        // red[0][0] dependency: fold into the counter address decision-free way
        unsigned int dummy = (__float_as_uint(red[0][0]) == 0x7f800001u) ? 1u : 0u;
        s_last = (atomicAdd(&g_count, 1u + dummy * 0u) == GRID - 1) ? 1u : 0u;
    }
    __syncthreads();

    if (s_last) {
        if (t < W_) {
            float r = __ldcg(&g_acc[t * PAD]);
            out[t] = -r;
            g_acc[t * PAD] = 0.0f;        // restore zero state for replay
        }
        if (t == 0) g_count = 0u;
    }
}

extern "C" void kernel_launch(void* const* d_in, const int* in_sizes, int n_in,
                              void* d_out, int out_size) {
    const float* x = (const float*)d_in[0];
    const float* y = (const float*)d_in[1];
    float* out = (float*)d_out;

    mce_tiled_kernel<<<GRID, TPB>>>(x, y, out);
}

// round 16
// speedup vs baseline: 1.0037x; 1.0037x over previous
#include <cuda_runtime.h>
#include <cuda_bf16.h>

// Problem: MultinomialCELoss
//   x: [N=8, Q=441, H=128, W=128] f32, y: [N=8, 2, H=128, W=128] f32
//   out[w] = -sum_{n,h} log( x[n, idx(n,h,w), h, w] )
//
// R16: structure is settled (R11/R14: one CTA per output element, zero
// inter-CTA communication — every combine alternative costs ~2us). ncu is
// cold-cache (--cache-control all) so only bench dur adjudicates warm tuning.
// Knobs this round: (1) MLP 2->4 (TPB 256, 4 rows/thread) — same outstanding
// loads per SM, deeper per-warp batching, shorter tree; (2) precompute gather
// base pointers before y arrives so the post-y chain is just bin->shift->LDG.

#define N_  8
#define Q_  441
#define H_  128
#define W_  128
#define HW_ (H_ * W_)
#define NBINS 21
#define TPB 256
#define RPT 4                 // rows per thread: 1024 rows / 256 threads

__device__ __forceinline__ int ab_bin(float v) {
    // Match JAX f32 semantics: floor((v + 110) / 10), clipped to [0,20].
    // __fdiv_rn keeps IEEE division even under fast-math (bin boundaries).
    float q = floorf(__fdiv_rn(v + 110.0f, 10.0f));
    int qi = (int)q;
    qi = qi < 0 ? 0 : qi;
    qi = qi > (NBINS - 1) ? (NBINS - 1) : qi;
    return qi;
}

__global__ __launch_bounds__(TPB) void mce_column_kernel(
    const float* __restrict__ x,
    const float* __restrict__ y,
    float* __restrict__ out)
{
    const int w = blockIdx.x;     // 0..127: this CTA owns out[w]
    const int t = threadIdx.x;    // 0..255

    // Thread t handles rows t, t+256, t+512, t+768.
    // Precompute everything that does not depend on y, so the only work
    // between y arrival and gather issue is bin math + shift + add.
    const float* ybase[RPT * 2];
    const float* xbase[RPT];
    #pragma unroll
    for (int k = 0; k < RPT; k++) {
        const int row = t + k * TPB;         // 0..1023
        const int n = row >> 7;
        const int h = row & (H_ - 1);
        const int hw = h * W_ + w;
        ybase[2 * k + 0] = y + (size_t)(n * 2 + 0) * HW_ + hw;
        ybase[2 * k + 1] = y + (size_t)(n * 2 + 1) * HW_ + hw;
        xbase[k] = x + (size_t)n * Q_ * HW_ + hw;   // + idx*HW_ remains
    }

    // 8 independent y loads issued back-to-back.
    float ya[RPT], yb[RPT];
    #pragma unroll
    for (int k = 0; k < RPT; k++) {
        ya[k] = *ybase[2 * k + 0];
        yb[k] = *ybase[2 * k + 1];
    }

    // 4 independent scattered gathers issued back-to-back (MLP=4).
    float v[RPT];
    #pragma unroll
    for (int k = 0; k < RPT; k++) {
        const int idx = ab_bin(ya[k]) * NBINS + ab_bin(yb[k]);
        v[k] = __ldcg(xbase[k] + (size_t)idx * HW_);
    }

    float s = 0.0f;
    #pragma unroll
    for (int k = 0; k < RPT; k++) s += __logf(v[k]);

    // Intra-block tree: warp shuffle, then 8 warp sums through smem.
    #pragma unroll
    for (int off = 16; off > 0; off >>= 1)
        s += __shfl_down_sync(0xffffffffu, s, off);

    __shared__ float red[TPB / 32];          // 8 warp partials
    if ((t & 31) == 0) red[t >> 5] = s;
    __syncthreads();

    if (t < 32) {
        float r = (t < TPB / 32) ? red[t] : 0.0f;
        #pragma unroll
        for (int off = 4; off > 0; off >>= 1)
            r += __shfl_down_sync(0xffffffffu, r, off);
        if (t == 0) out[w] = -r;
    }
}

extern "C" void kernel_launch(void* const* d_in, const int* in_sizes, int n_in,
                              void* d_out, int out_size) {
    const float* x = (const float*)d_in[0];
    const float* y = (const float*)d_in[1];
    float* out = (float*)d_out;

    mce_column_kernel<<<W_, TPB>>>(x, y, out);
}